// round 13
// baseline (speedup 1.0000x reference)
#include <cuda_runtime.h>
#include <cstdint>
#include <cstddef>

#define BB 64
#define TT 512
#define DD 600
#define DA 300
#define UU 300
#define HH 5
#define EPS_F 1e-7f
#define NCH 8          // t-chunks in fused pass
#define TCH (TT/NCH)   // 64 t per chunk
#define GRB 75         // recurrence grid (all co-resident, <=148 SMs)

// fused v4 dynamic smem (floats): ws[3000] rowbuf[4800] lpart[128] zpart[32]
#define FUSED_SMEM_FLOATS (3000 + 4800 + 128 + 32)
#define FUSED_SMEM_BYTES  (FUSED_SMEM_FLOATS * 4)
// dynamic smem for recur_kernel: e_sh[19200] + w1[8*308] + w2[4*308]
#define RECUR_SMEM_FLOATS (19200 + 8 * 308 + 4 * 308)
#define RECUR_SMEM_BYTES  (RECUR_SMEM_FLOATS * 4)

// ---------------- device scratch ----------------
__device__ float g_IALpart[NCH * HH * BB * DD];   // per-chunk partial unnormalized i_al
__device__ float g_Zpart[NCH * HH * BB];          // per-chunk partial sum of exp
__device__ float g_IAL[HH * BB * DD];             // normalized i_al
__device__ float g_Pconst[HH * BB * 900];         // [r|z|c] preacts from i_al
__device__ float4 g_e4[BB * UU / 4];              // recurrent state (16B aligned)
__device__ float4 g_rE4[BB * UU / 4];             // r * e
__device__ float g_z[BB * UU];                    // z gate
__device__ unsigned g_cnt = 0;                    // grid barrier
__device__ volatile unsigned g_gen = 0;

__device__ __forceinline__ void cp_async16(void* smem_dst, const void* gmem_src) {
    unsigned sdst = (unsigned)__cvta_generic_to_shared(smem_dst);
    asm volatile("cp.async.cg.shared.global [%0], [%1], 16;" :: "r"(sdst), "l"(gmem_src));
}
#define CP_COMMIT() asm volatile("cp.async.commit_group;")

// ---------------- kernel 1: fused logits+exp+weighted-sum, warp-pair autonomous ----------
// grid (NCH, BB) x 256 = 8 warps = 4 pairs. Pair p: rows {p+4j, j<16}. Warp q of pair:
// d-half [300q, 300q+300). Per-warp cp.async double buffer; one 64-thread named barrier
// per row (logit partial exchange); register accumulators; 3-barrier epilogue tree.
__global__ void __launch_bounds__(256, 2)
fused_kernel(const float* __restrict__ memory, const float* __restrict__ al_w) {
    extern __shared__ float sm[];
    float* ws     = sm;            // 3000: ws[h*600+d]
    float* rowbuf = sm + 3000;     // 4800: per warp 600 (2 slots x 300)
    float* lpart  = sm + 7800;     // 128: [jpar][pair][q][h] = jpar*64+(pair*2+q)*8+h
    float* zpart  = sm + 7928;     // 32: [pair][h]

    int chunk = blockIdx.x;
    int b = blockIdx.y;
    int tid = threadIdx.x;
    int wid = tid >> 5;
    int lane = tid & 31;
    int pair = wid >> 1;
    int q = wid & 1;
    int barid = pair + 1;

    for (int i = tid; i < 3000; i += 256) {
        int h = i / 600, d = i % 600;
        ws[i] = al_w[h * 1200 + d];
    }
    const float4* ws4 = (const float4*)ws;

    float* slot0 = rowbuf + wid * 600;
    float* slot1 = slot0 + 300;
    const float* gmem = memory + ((size_t)b * TT + chunk * TCH) * DD + q * 300;

    // prefetch row j=0 (row index = pair)
    {
        const float4* src = (const float4*)(gmem + (size_t)pair * DD);
        float4* dst = (float4*)slot0;
        for (int m = lane; m < 75; m += 32) cp_async16(&dst[m], &src[m]);
        CP_COMMIT();
    }
    __syncthreads();   // ws visible to all

    float macc[HH][10];
#pragma unroll
    for (int h = 0; h < HH; h++)
#pragma unroll
        for (int jj = 0; jj < 10; jj++) macc[h][jj] = 0.f;
    float zacc[HH] = {0.f, 0.f, 0.f, 0.f, 0.f};

#pragma unroll 1
    for (int j = 0; j < 16; j++) {
        float* curs = (j & 1) ? slot1 : slot0;
        float* nxts = (j & 1) ? slot0 : slot1;
        if (j < 15) {
            const float4* src = (const float4*)(gmem + (size_t)(pair + 4 * (j + 1)) * DD);
            float4* dst = (float4*)nxts;
            for (int m = lane; m < 75; m += 32) cp_async16(&dst[m], &src[m]);
            CP_COMMIT();
            asm volatile("cp.async.wait_group 1;");
        } else {
            asm volatile("cp.async.wait_group 0;");
        }
        __syncwarp();

        // partial logits over my half
        float acc[HH] = {0.f, 0.f, 0.f, 0.f, 0.f};
        const float4* rv = (const float4*)curs;
#pragma unroll
        for (int mi = 0; mi < 3; mi++) {
            int m = lane + 32 * mi;
            if (m < 75) {
                float4 mr = rv[m];
#pragma unroll
                for (int h = 0; h < HH; h++) {
                    float4 w = ws4[h * 150 + q * 75 + m];
                    acc[h] += mr.x * w.x + mr.y * w.y + mr.z * w.z + mr.w * w.w;
                }
            }
        }
#pragma unroll
        for (int h = 0; h < HH; h++) {
#pragma unroll
            for (int off = 16; off > 0; off >>= 1)
                acc[h] += __shfl_xor_sync(0xffffffffu, acc[h], off);
        }
        int lbase = (j & 1) * 64 + (pair * 2 + q) * 8;
        if (lane == 0) {
#pragma unroll
            for (int h = 0; h < HH; h++) lpart[lbase + h] = acc[h];
        }
        asm volatile("bar.sync %0, 64;" :: "r"(barid) : "memory");

        // combined logit -> exp (lane0), broadcast
        float ex[HH];
        if (lane == 0) {
            int lb0 = (j & 1) * 64 + pair * 16;
#pragma unroll
            for (int h = 0; h < HH; h++)
                ex[h] = expf(lpart[lb0 + h] + lpart[lb0 + 8 + h]);
            if (q == 0) {
#pragma unroll
                for (int h = 0; h < HH; h++) zacc[h] += ex[h];
            }
        }
#pragma unroll
        for (int h = 0; h < HH; h++)
            ex[h] = __shfl_sync(0xffffffffu, ex[h], 0);

        // accumulate my half
#pragma unroll
        for (int jj = 0; jj < 10; jj++) {
            int dl = lane + 32 * jj;
            if (dl < 300) {
                float v = curs[dl];
#pragma unroll
                for (int h = 0; h < HH; h++) macc[h][jj] += ex[h] * v;
            }
        }
    }

    // ---- epilogue: combine 4 pairs ----
    if (q == 0 && lane == 0) {
#pragma unroll
        for (int h = 0; h < HH; h++) zpart[pair * 8 + h] = zacc[h];
    }
    __syncthreads();
    // pbuf[s][h*600+d] at sm + s*3000, s = pair&1 (ws+rowbuf are dead)
    float* pb = sm + (pair & 1) * 3000;
    if (pair < 2) {
#pragma unroll
        for (int jj = 0; jj < 10; jj++) {
            int dl = lane + 32 * jj;
            if (dl < 300) {
                int d = q * 300 + dl;
#pragma unroll
                for (int h = 0; h < HH; h++) pb[h * 600 + d] = macc[h][jj];
            }
        }
    }
    __syncthreads();
    if (pair >= 2) {
#pragma unroll
        for (int jj = 0; jj < 10; jj++) {
            int dl = lane + 32 * jj;
            if (dl < 300) {
                int d = q * 300 + dl;
#pragma unroll
                for (int h = 0; h < HH; h++) pb[h * 600 + d] += macc[h][jj];
            }
        }
    }
    __syncthreads();
    for (int i = tid; i < 3000; i += 256) {
        int h = i / 600, d = i % 600;
        g_IALpart[((size_t)(chunk * HH + h) * BB + b) * DD + d] = sm[i] + sm[3000 + i];
    }
    if (tid < HH) {
        float z = zpart[tid] + zpart[8 + tid] + zpart[16 + tid] + zpart[24 + tid];
        g_Zpart[(chunk * HH + tid) * BB + b] = z;
    }
}

// ---------------- kernel 2: reduce partials + normalize (deterministic) ----------------
__global__ void reduce_ial_kernel() {
    int i = blockIdx.x * 256 + threadIdx.x;
    int hb = i / DD;
    int h = hb / BB;
    int b = hb - h * BB;
    float s = 0.f;
#pragma unroll
    for (int c = 0; c < NCH; c++) s += g_IALpart[(size_t)c * (HH * BB * DD) + i];
    float z = 0.f;
#pragma unroll
    for (int c = 0; c < NCH; c++) z += g_Zpart[(c * HH + h) * BB + b];
    g_IAL[i] = s / (z + EPS_F);
}

// ---------------- kernel 3: Pconst = IAL @ [Wr|Wz|Wx]  (M=320, K=600, N=900) ----------------
__global__ void pconst_kernel(const float* __restrict__ wr, const float* __restrict__ wz,
                              const float* __restrict__ wx) {
    __shared__ float Xs[32][65];
    __shared__ float Ws[32][33];
    int n0 = blockIdx.x * 32;
    int h = blockIdx.y;
    int tid = threadIdx.x;
    int tu = tid & 15;
    int tb = tid >> 4;

    float acc[4][2] = {};
    for (int kc = 0; kc < DD; kc += 32) {
        {
            int kk = tid & 31;
            int br = tid >> 5;
            int k = kc + kk;
#pragma unroll
            for (int j = 0; j < 8; j++) {
                int b = br + 8 * j;
                Xs[kk][b] = (k < DD) ? g_IAL[((size_t)(h * BB + b)) * DD + k] : 0.f;
            }
        }
        {
            int u = tid & 31;
            int kr = tid >> 5;
            int n = n0 + u;
#pragma unroll
            for (int j = 0; j < 4; j++) {
                int kk2 = kr + 8 * j;
                int kg = kc + kk2;
                float v = 0.f;
                if (kg < DD && n < 900) {
                    if (n < 300)      v = wr[kg * UU + n];
                    else if (n < 600) v = wz[kg * UU + (n - 300)];
                    else              v = wx[kg * UU + (n - 600)];
                }
                Ws[kk2][u] = v;
            }
        }
        __syncthreads();
#pragma unroll
        for (int kk3 = 0; kk3 < 32; kk3++) {
            float xv[4], wv[2];
#pragma unroll
            for (int i = 0; i < 4; i++) xv[i] = Xs[kk3][tb * 4 + i];
#pragma unroll
            for (int j = 0; j < 2; j++) wv[j] = Ws[kk3][tu * 2 + j];
#pragma unroll
            for (int i = 0; i < 4; i++)
#pragma unroll
                for (int j = 0; j < 2; j++) acc[i][j] += xv[i] * wv[j];
        }
        __syncthreads();
    }
#pragma unroll
    for (int i = 0; i < 4; i++) {
        int b = tb * 4 + i;
#pragma unroll
        for (int j = 0; j < 2; j++) {
            int n = n0 + tu * 2 + j;
            if (n < 900) g_Pconst[((size_t)(h * BB + b)) * 900 + n] = acc[i][j];
        }
    }
}

// ---------------- grid barrier (GRB blocks, all co-resident) ----------------
__device__ __forceinline__ void grid_barrier() {
    __syncthreads();
    if (threadIdx.x == 0) {
        __threadfence();
        unsigned my = g_gen;
        if (atomicAdd(&g_cnt, 1) == GRB - 1) {
            g_cnt = 0;
            __threadfence();
            g_gen = my + 1;
        } else {
            while (g_gen == my) { }
        }
    }
    __syncthreads();
}

// ---------------- kernel 4: persistent 5-hop GRU recurrence, output-per-thread ----------------
__global__ void __launch_bounds__(512, 1)
recur_kernel(const float* __restrict__ ur, const float* __restrict__ uz,
             const float* __restrict__ wg, float* __restrict__ out) {
    extern __shared__ float rs[];
    float* e_sh = rs;                    // 19200 floats
    float4* e4 = (float4*)rs;            // 4800 float4
    float* w1_sh = rs + 19200;           // 8 * 308
    float* w2_sh = rs + 19200 + 8 * 308; // 4 * 308

    int tid = threadIdx.x;
    int bid = blockIdx.x;

    for (int i = tid; i < 2400; i += 512) {
        int k = i >> 3, j = i & 7;
        int n = bid * 8 + j;
        float v = (n < 300) ? ur[k * UU + n] : uz[k * UU + (n - 300)];
        w1_sh[j * 308 + k] = v;
    }
    for (int i = tid; i < 1200; i += 512) {
        int k = i >> 2, j = i & 3;
        w2_sh[j * 308 + k] = wg[k * UU + bid * 4 + j];
    }
    {
        int i = bid * 512 + tid;
        if (i < BB * UU) {
            float zz = 0.f;
            asm volatile("st.global.cg.f32 [%0], %1;" :: "l"((float*)g_e4 + i), "f"(zz));
        }
    }
    grid_barrier();

    int n1 = bid * 8 + (tid & 7);
    int b1 = tid >> 3;
    int n2 = bid * 4 + (tid & 3);
    int b2 = tid >> 2;
    const float4* wv1 = (const float4*)(w1_sh + (tid & 7) * 308);
    const float4* wv2 = (const float4*)(w2_sh + (tid & 3) * 308);

#pragma unroll 1
    for (int h = 0; h < HH; h++) {
        for (int i = tid; i < 4800; i += 512)
            e4[i] = __ldcg(g_e4 + i);
        __syncthreads();
        {
            const float4* ev = e4 + b1 * 75;
            float ax = 0.f, ay = 0.f, az = 0.f, aw = 0.f;
#pragma unroll
            for (int qq = 0; qq < 75; qq++) {
                float4 e = ev[qq];
                float4 w = wv1[qq];
                ax += e.x * w.x; ay += e.y * w.y;
                az += e.z * w.z; aw += e.w * w.w;
            }
            float acc = (ax + ay) + (az + aw);
            float p = __ldg(g_Pconst + ((size_t)(h * BB + b1)) * 900 + ((n1 < 300) ? n1 : 300 + (n1 - 300) + 300) );
            // note: pcOff = n1 for r (n1<300), 300+(n1-300)=n1 for z — identical: offset n1
            p = __ldg(g_Pconst + ((size_t)(h * BB + b1)) * 900 + n1);
            float s = 1.0f / (1.0f + expf(-(p + acc)));
            if (n1 < 300) {
                float ev1 = e_sh[b1 * UU + n1];
                __stcg((float*)g_rE4 + b1 * UU + n1, s * ev1);
            } else {
                __stcg(g_z + b1 * UU + (n1 - 300), s);
            }
        }
        grid_barrier();
        for (int i = tid; i < 4800; i += 512)
            e4[i] = __ldcg(g_rE4 + i);
        __syncthreads();
        if (tid < 256) {
            const float4* rv = e4 + b2 * 75;
            float ax = 0.f, ay = 0.f, az = 0.f, aw = 0.f;
#pragma unroll
            for (int qq = 0; qq < 75; qq++) {
                float4 r = rv[qq];
                float4 w = wv2[qq];
                ax += r.x * w.x; ay += r.y * w.y;
                az += r.z * w.z; aw += r.w * w.w;
            }
            float acc = (ax + ay) + (az + aw);
            float p = __ldg(g_Pconst + ((size_t)(h * BB + b2)) * 900 + 600 + n2);
            float et = tanhf(p + acc);
            float zv, ev;
            float* ep = (float*)g_e4 + b2 * UU + n2;
            asm volatile("ld.global.cg.f32 %0, [%1];" : "=f"(ev) : "l"(ep));
            asm volatile("ld.global.cg.f32 %0, [%1];" : "=f"(zv) : "l"(g_z + b2 * UU + n2));
            float o = (1.0f - zv) * ev + zv * et;
            asm volatile("st.global.cg.f32 [%0], %1;" :: "l"(ep), "f"(o));
            if (h == HH - 1) out[b2 * UU + n2] = o;
        }
        grid_barrier();
    }
}

// ---------------- launch ----------------
extern "C" void kernel_launch(void* const* d_in, const int* in_sizes, int n_in,
                              void* d_out, int out_size) {
    const float* memory = nullptr;  // 19660800
    const float* al_w   = nullptr;  // 6000
    const float* w180[3] = {nullptr, nullptr, nullptr};  // wr, wz, wx
    const float* w90[3]  = {nullptr, nullptr, nullptr};  // ur, uz, wg
    int n180 = 0, n90 = 0;
    for (int i = 0; i < n_in; i++) {
        const float* p = (const float*)d_in[i];
        switch (in_sizes[i]) {
            case 19660800: memory = p; break;
            case 6000:     al_w = p;   break;
            case 180000:   if (n180 < 3) w180[n180++] = p; break;
            case 90000:    if (n90 < 3)  w90[n90++]  = p; break;
            default: break;
        }
    }
    const float* gru_wr = w180[0];
    const float* gru_wz = w180[1];
    const float* gru_wx = w180[2];
    const float* gru_ur = w90[0];
    const float* gru_uz = w90[1];
    const float* gru_wg = w90[2];
    float* out = (float*)d_out;

    cudaFuncSetAttribute(fused_kernel, cudaFuncAttributeMaxDynamicSharedMemorySize,
                         FUSED_SMEM_BYTES);
    cudaFuncSetAttribute(recur_kernel, cudaFuncAttributeMaxDynamicSharedMemorySize,
                         RECUR_SMEM_BYTES);

    fused_kernel<<<dim3(NCH, BB), 256, FUSED_SMEM_BYTES>>>(memory, al_w);
    reduce_ial_kernel<<<(HH * BB * DD) / 256, 256>>>();
    pconst_kernel<<<dim3(29, HH), 256>>>(gru_wr, gru_wz, gru_wx);
    recur_kernel<<<GRB, 512, RECUR_SMEM_BYTES>>>(gru_ur, gru_uz, gru_wg, out);
}

// round 15
// speedup vs baseline: 1.1928x; 1.1928x over previous
#include <cuda_runtime.h>
#include <cstdint>
#include <cstddef>

#define BB 64
#define TT 512
#define DD 600
#define DA 300
#define UU 300
#define HH 5
#define EPS_F 1e-7f
#define NCH 8          // t-chunks in fused pass
#define TCH (TT/NCH)   // 64 t per chunk
#define GRB 75         // recurrence grid (all co-resident, <=148 SMs)

// fused (R12 v3) dynamic smem (floats): ws[3000] rows[2][4800] wexp[64] zsh[64]
#define FUSED_SMEM_FLOATS (3000 + 2 * 4800 + 64 + 64)
#define FUSED_SMEM_BYTES  (FUSED_SMEM_FLOATS * 4)
// dynamic smem for recur_kernel: e_sh[19200] + w1[8*308] + w2[4*308]
#define RECUR_SMEM_FLOATS (19200 + 8 * 308 + 4 * 308)
#define RECUR_SMEM_BYTES  (RECUR_SMEM_FLOATS * 4)

// ---------------- device scratch ----------------
__device__ float g_IALpart[NCH * HH * BB * DD];   // per-chunk partial unnormalized i_al
__device__ float g_Zpart[NCH * HH * BB];          // per-chunk partial sum of exp
__device__ float g_IAL[HH * BB * DD];             // normalized i_al
__device__ float g_Pconst[HH * BB * 900];         // [r|z|c] preacts from i_al
__device__ float4 g_e4[BB * UU / 4];              // recurrent state (16B aligned)
__device__ float4 g_rE4[BB * UU / 4];             // r * e
__device__ float g_z[BB * UU];                    // z gate
__device__ unsigned g_cnt = 0;                    // grid barrier counter (proven R10-R13)
__device__ volatile unsigned g_gen = 0;           // grid barrier generation

__device__ __forceinline__ void cp_async16(void* smem_dst, const void* gmem_src) {
    unsigned sdst = (unsigned)__cvta_generic_to_shared(smem_dst);
    asm volatile("cp.async.cg.shared.global [%0], [%1], 16;" :: "r"(sdst), "l"(gmem_src));
}
#define CP_COMMIT() asm volatile("cp.async.commit_group;")

// ---------------- kernel 1: fused logits+exp+weighted-sum (R12 v3, proven) ------------
__global__ void __launch_bounds__(256, 4)
fused_kernel(const float* __restrict__ memory, const float* __restrict__ al_w) {
    extern __shared__ float smem[];
    float* ws = smem;                              // 3000 floats
    float4* rowsA = (float4*)(smem + 3000);        // 1200 float4
    float4* rowsB = (float4*)(smem + 3000 + 4800); // 1200 float4
    float* wexp = smem + 3000 + 9600;              // [8][8]
    float* zsh  = wexp + 64;                       // [8][8]

    int chunk = blockIdx.x;
    int b = blockIdx.y;
    int tid = threadIdx.x;
    int wid = tid >> 5;
    int lane = tid & 31;
    int t0 = chunk * TCH;
    const float4* gbase = reinterpret_cast<const float4*>(memory + ((size_t)b * TT + t0) * DD);

#pragma unroll
    for (int i = 0; i < 5; i++) {
        int idx = tid + 256 * i;
        if (idx < 1200) cp_async16(&rowsA[idx], gbase + idx);
    }
    CP_COMMIT();

    for (int i = tid; i < HH * DD; i += 256) {
        int h = i / DD, d = i % DD;
        ws[i] = al_w[h * 1200 + d];
    }
    const float4* ws4 = reinterpret_cast<const float4*>(ws);

    int d0 = tid, d1 = tid + 256, d2 = tid + 512;
    bool has2 = (d2 < DD);
    float macc[HH][3];
#pragma unroll
    for (int h = 0; h < HH; h++) { macc[h][0]=0.f; macc[h][1]=0.f; macc[h][2]=0.f; }
    float zacc[HH] = {0.f,0.f,0.f,0.f,0.f};

#pragma unroll 1
    for (int grp = 0; grp < 8; grp++) {
        float4* cur = (grp & 1) ? rowsB : rowsA;
        float4* nxt = (grp & 1) ? rowsA : rowsB;
        if (grp < 7) {
#pragma unroll
            for (int i = 0; i < 5; i++) {
                int idx = tid + 256 * i;
                if (idx < 1200) cp_async16(&nxt[idx], gbase + (grp + 1) * 1200 + idx);
            }
            CP_COMMIT();
            asm volatile("cp.async.wait_group 1;");
        } else {
            asm volatile("cp.async.wait_group 0;");
        }
        __syncthreads();
        // ---- stage A: warp per row ----
        {
            const float4* rrow = &cur[wid * 150];
            float acc[HH] = {0.f,0.f,0.f,0.f,0.f};
#pragma unroll
            for (int i = 0; i < 5; i++) {
                int i4 = lane + 32 * i;
                if (i4 < 150) {
                    float4 m = rrow[i4];
#pragma unroll
                    for (int h = 0; h < HH; h++) {
                        float4 w = ws4[h * 150 + i4];
                        acc[h] += m.x*w.x + m.y*w.y + m.z*w.z + m.w*w.w;
                    }
                }
            }
#pragma unroll
            for (int h = 0; h < HH; h++) {
#pragma unroll
                for (int off = 16; off > 0; off >>= 1)
                    acc[h] += __shfl_xor_sync(0xffffffffu, acc[h], off);
            }
            if (lane == 0) {
#pragma unroll
                for (int h = 0; h < HH; h++) {
                    float ex = expf(acc[h]);
                    wexp[wid * 8 + h] = ex;
                    zacc[h] += ex;
                }
            }
        }
        __syncthreads();
        // ---- stage B: accumulate weighted rows ----
        const float* rf = reinterpret_cast<const float*>(cur);
#pragma unroll
        for (int r = 0; r < 8; r++) {
            float m0 = rf[r * DD + d0];
            float m1 = rf[r * DD + d1];
            float m2 = has2 ? rf[r * DD + d2] : 0.f;
#pragma unroll
            for (int h = 0; h < HH; h++) {
                float a = wexp[r * 8 + h];
                macc[h][0] += a * m0;
                macc[h][1] += a * m1;
                macc[h][2] += a * m2;
            }
        }
        __syncthreads();
    }

    if (lane == 0) {
#pragma unroll
        for (int h = 0; h < HH; h++) zsh[wid * 8 + h] = zacc[h];
    }
    __syncthreads();
    if (tid < HH) {
        float z = 0.f;
#pragma unroll
        for (int w = 0; w < 8; w++) z += zsh[w * 8 + tid];
        g_Zpart[(chunk * HH + tid) * BB + b] = z;
    }
#pragma unroll
    for (int h = 0; h < HH; h++) {
        float* dst = g_IALpart + ((size_t)(chunk * HH + h) * BB + b) * DD;
        dst[d0] = macc[h][0];
        dst[d1] = macc[h][1];
        if (has2) dst[d2] = macc[h][2];
    }
}

// ---------------- kernel 2: reduce partials + normalize (deterministic) ----------------
__global__ void reduce_ial_kernel() {
    int i = blockIdx.x * 256 + threadIdx.x;
    int hb = i / DD;
    int h = hb / BB;
    int b = hb - h * BB;
    float s = 0.f;
#pragma unroll
    for (int c = 0; c < NCH; c++) s += g_IALpart[(size_t)c * (HH * BB * DD) + i];
    float z = 0.f;
#pragma unroll
    for (int c = 0; c < NCH; c++) z += g_Zpart[(c * HH + h) * BB + b];
    g_IAL[i] = s / (z + EPS_F);
}

// ---------------- kernel 3: Pconst = IAL @ [Wr|Wz|Wx]  (M=320, K=600, N=900) ----------------
__global__ void pconst_kernel(const float* __restrict__ wr, const float* __restrict__ wz,
                              const float* __restrict__ wx) {
    __shared__ float Xs[32][65];
    __shared__ float Ws[32][33];
    int n0 = blockIdx.x * 32;
    int h = blockIdx.y;
    int tid = threadIdx.x;
    int tu = tid & 15;
    int tb = tid >> 4;

    float acc[4][2] = {};
    for (int kc = 0; kc < DD; kc += 32) {
        {
            int kk = tid & 31;
            int br = tid >> 5;
            int k = kc + kk;
#pragma unroll
            for (int j = 0; j < 8; j++) {
                int b = br + 8 * j;
                Xs[kk][b] = (k < DD) ? g_IAL[((size_t)(h * BB + b)) * DD + k] : 0.f;
            }
        }
        {
            int u = tid & 31;
            int kr = tid >> 5;
            int n = n0 + u;
#pragma unroll
            for (int j = 0; j < 4; j++) {
                int kk2 = kr + 8 * j;
                int kg = kc + kk2;
                float v = 0.f;
                if (kg < DD && n < 900) {
                    if (n < 300)      v = wr[kg * UU + n];
                    else if (n < 600) v = wz[kg * UU + (n - 300)];
                    else              v = wx[kg * UU + (n - 600)];
                }
                Ws[kk2][u] = v;
            }
        }
        __syncthreads();
#pragma unroll
        for (int kk3 = 0; kk3 < 32; kk3++) {
            float xv[4], wv[2];
#pragma unroll
            for (int i = 0; i < 4; i++) xv[i] = Xs[kk3][tb * 4 + i];
#pragma unroll
            for (int j = 0; j < 2; j++) wv[j] = Ws[kk3][tu * 2 + j];
#pragma unroll
            for (int i = 0; i < 4; i++)
#pragma unroll
                for (int j = 0; j < 2; j++) acc[i][j] += xv[i] * wv[j];
        }
        __syncthreads();
    }
#pragma unroll
    for (int i = 0; i < 4; i++) {
        int b = tb * 4 + i;
#pragma unroll
        for (int j = 0; j < 2; j++) {
            int n = n0 + tu * 2 + j;
            if (n < 900) g_Pconst[((size_t)(h * BB + b)) * 900 + n] = acc[i][j];
        }
    }
}

// ---------------- grid barrier (proven R10-R13: atomicAdd + volatile generation) ----------
__device__ __forceinline__ void grid_barrier() {
    __syncthreads();
    if (threadIdx.x == 0) {
        __threadfence();
        unsigned my = g_gen;
        if (atomicAdd(&g_cnt, 1) == GRB - 1) {
            g_cnt = 0;
            __threadfence();
            g_gen = my + 1;
        } else {
            while (g_gen == my) { }
        }
    }
    __syncthreads();
}

// ---------------- kernel 4: persistent GRU recurrence (hop1 elementwise shortcut) -----------
// grid 75 x 512. e0=0 => hop1: e1 = sigmoid(Pc_z) * tanh(Pc_c), elementwise, no init phase.
// Hops 2..5: phase1 (r,z GEMV) + phase2 (candidate GEMV + update). 8 barriers total.
__global__ void __launch_bounds__(512, 1)
recur_kernel(const float* __restrict__ ur, const float* __restrict__ uz,
             const float* __restrict__ wg, float* __restrict__ out) {
    extern __shared__ float rs[];
    float* e_sh = rs;                    // 19200 floats
    float4* e4 = (float4*)rs;            // 4800 float4
    float* w1_sh = rs + 19200;           // 8 * 308
    float* w2_sh = rs + 19200 + 8 * 308; // 4 * 308

    int tid = threadIdx.x;
    int bid = blockIdx.x;

    for (int i = tid; i < 2400; i += 512) {
        int k = i >> 3, j = i & 7;
        int n = bid * 8 + j;
        float v = (n < 300) ? ur[k * UU + n] : uz[k * UU + (n - 300)];
        w1_sh[j * 308 + k] = v;
    }
    for (int i = tid; i < 1200; i += 512) {
        int k = i >> 2, j = i & 3;
        w2_sh[j * 308 + k] = wg[k * UU + bid * 4 + j];
    }

    int n1 = bid * 8 + (tid & 7);
    int b1 = tid >> 3;
    int n2 = bid * 4 + (tid & 3);
    int b2 = tid >> 2;
    const float4* wv1 = (const float4*)(w1_sh + (tid & 7) * 308);
    const float4* wv2 = (const float4*)(w2_sh + (tid & 3) * 308);

    // ---- hop 1: elementwise (e0 = 0 => e1 = sigmoid(Pz) * tanh(Pc)) ----
    if (tid < 256) {
        float pz = __ldg(g_Pconst + (size_t)b2 * 900 + 300 + n2);
        float pc = __ldg(g_Pconst + (size_t)b2 * 900 + 600 + n2);
        float z = 1.0f / (1.0f + expf(-pz));
        float e1 = z * tanhf(pc);
        asm volatile("st.global.cg.f32 [%0], %1;"
                     :: "l"((float*)g_e4 + b2 * UU + n2), "f"(e1));
    }
    grid_barrier();

    // ---- hops 2..5 ----
#pragma unroll 1
    for (int h = 1; h < HH; h++) {
        // phase 1: r,z = sigmoid(Pconst + e @ [Ur|Uz])
        {
            float p;
            asm volatile("ld.global.nc.f32 %0, [%1];" : "=f"(p)
                         : "l"(g_Pconst + ((size_t)(h * BB + b1)) * 900 + n1));
            for (int i = tid; i < 4800; i += 512)
                e4[i] = __ldcg(g_e4 + i);
            __syncthreads();
            const float4* ev = e4 + b1 * 75;
            float ax = 0.f, ay = 0.f, az = 0.f, aw = 0.f;
#pragma unroll
            for (int qq = 0; qq < 75; qq++) {
                float4 e = ev[qq];
                float4 w = wv1[qq];
                ax += e.x * w.x; ay += e.y * w.y;
                az += e.z * w.z; aw += e.w * w.w;
            }
            float acc = (ax + ay) + (az + aw);
            float s = 1.0f / (1.0f + expf(-(p + acc)));
            if (n1 < 300) {
                float ev1 = e_sh[b1 * UU + n1];
                __stcg((float*)g_rE4 + b1 * UU + n1, s * ev1);
            } else {
                __stcg(g_z + b1 * UU + (n1 - 300), s);
            }
        }
        grid_barrier();
        // phase 2: e = (1-z)e + z*tanh(Pconst_c + rE @ Wg)
        {
            float p = 0.f;
            if (tid < 256)
                asm volatile("ld.global.nc.f32 %0, [%1];" : "=f"(p)
                             : "l"(g_Pconst + ((size_t)(h * BB + b2)) * 900 + 600 + n2));
            for (int i = tid; i < 4800; i += 512)
                e4[i] = __ldcg(g_rE4 + i);
            __syncthreads();
            if (tid < 256) {
                const float4* rv = e4 + b2 * 75;
                float ax = 0.f, ay = 0.f, az = 0.f, aw = 0.f;
#pragma unroll
                for (int qq = 0; qq < 75; qq++) {
                    float4 r = rv[qq];
                    float4 w = wv2[qq];
                    ax += r.x * w.x; ay += r.y * w.y;
                    az += r.z * w.z; aw += r.w * w.w;
                }
                float acc = (ax + ay) + (az + aw);
                float et = tanhf(p + acc);
                float zv, ev;
                float* ep = (float*)g_e4 + b2 * UU + n2;
                asm volatile("ld.global.cg.f32 %0, [%1];" : "=f"(ev) : "l"(ep));
                asm volatile("ld.global.cg.f32 %0, [%1];" : "=f"(zv) : "l"(g_z + b2 * UU + n2));
                float o = (1.0f - zv) * ev + zv * et;
                if (h == HH - 1) {
                    out[b2 * UU + n2] = o;
                } else {
                    asm volatile("st.global.cg.f32 [%0], %1;" :: "l"(ep), "f"(o));
                }
            }
            if (h < HH - 1) grid_barrier();
        }
    }
}

// ---------------- launch ----------------
extern "C" void kernel_launch(void* const* d_in, const int* in_sizes, int n_in,
                              void* d_out, int out_size) {
    const float* memory = nullptr;  // 19660800
    const float* al_w   = nullptr;  // 6000
    const float* w180[3] = {nullptr, nullptr, nullptr};  // wr, wz, wx
    const float* w90[3]  = {nullptr, nullptr, nullptr};  // ur, uz, wg
    int n180 = 0, n90 = 0;
    for (int i = 0; i < n_in; i++) {
        const float* p = (const float*)d_in[i];
        switch (in_sizes[i]) {
            case 19660800: memory = p; break;
            case 6000:     al_w = p;   break;
            case 180000:   if (n180 < 3) w180[n180++] = p; break;
            case 90000:    if (n90 < 3)  w90[n90++]  = p; break;
            default: break;
        }
    }
    const float* gru_wr = w180[0];
    const float* gru_wz = w180[1];
    const float* gru_wx = w180[2];
    const float* gru_ur = w90[0];
    const float* gru_uz = w90[1];
    const float* gru_wg = w90[2];
    float* out = (float*)d_out;

    cudaFuncSetAttribute(fused_kernel, cudaFuncAttributeMaxDynamicSharedMemorySize,
                         FUSED_SMEM_BYTES);
    cudaFuncSetAttribute(recur_kernel, cudaFuncAttributeMaxDynamicSharedMemorySize,
                         RECUR_SMEM_BYTES);

    fused_kernel<<<dim3(NCH, BB), 256, FUSED_SMEM_BYTES>>>(memory, al_w);
    reduce_ial_kernel<<<(HH * BB * DD) / 256, 256>>>();
    pconst_kernel<<<dim3(29, HH), 256>>>(gru_wr, gru_wz, gru_wx);
    recur_kernel<<<GRB, 512, RECUR_SMEM_BYTES>>>(gru_ur, gru_uz, gru_wg, out);
}